// round 11
// baseline (speedup 1.0000x reference)
#include <cuda_runtime.h>
#include <cuda_fp16.h>
#include <cstdint>

// ---------------- problem constants ----------------
#define BATCH    64
#define INCH     8192
#define OUTCH    8192
#define NT       64             // out-channel tile per CTA
#define KT       64             // K tile (64 fp16 = 128B row)
#define NITER    (INCH / KT)    // 128
#define NTHREADS 512
#define NCTAS    (OUTCH / NT)   // 128

// W fp32 ring: 5 stages x 64 rows x 320B pitch = 102400
// A fp16 ring: 5 stages x 8192 ; B sign ring: 2 stages x 8192
// 5-stage ring => smem stage recycled 2 sync-windows after last read (race-free;
// 4-stage recycles after 1 window and races with lagging warps' LDSM/LDS).
#define W_PITCH     320
#define W_STAGE     (64 * W_PITCH)
#define SMEM_W      0
#define SMEM_A      (5 * W_STAGE)            // 102400
#define SMEM_B      (SMEM_A + 5 * 8192)      // 143360
#define SMEM_BYTES  (SMEM_B + 2 * 8192)      // 159744

__device__ __half g_xhalf[(size_t)BATCH * INCH];   // fp16 plane of x
__device__ float g_abssum;
__device__ int   g_done;

// ---------------- helpers ----------------
__device__ __forceinline__ uint32_t smem_u32(const void* p) {
    uint32_t a;
    asm("{ .reg .u64 t; cvta.to.shared.u64 t, %1; cvt.u32.u64 %0, t; }" : "=r"(a) : "l"(p));
    return a;
}

#define SW128(off) ((off) ^ (((off) >> 3) & 0x70))

// sign(w) as fp16: +1 / -1 / 0
__device__ __forceinline__ uint32_t sgn_f16(float w) {
    uint32_t u = __float_as_uint(w);
    return (w == 0.0f) ? 0u : (0x3C00u | ((u >> 16) & 0x8000u));
}

__device__ __forceinline__ void ldsm_x4(uint32_t* r, uint32_t addr) {
    asm volatile("ldmatrix.sync.aligned.m8n8.x4.shared.b16 {%0,%1,%2,%3}, [%4];"
                 : "=r"(r[0]), "=r"(r[1]), "=r"(r[2]), "=r"(r[3]) : "r"(addr));
}

__device__ __forceinline__ void mma_f16(float* c, const uint32_t* a, const uint32_t* b) {
    asm volatile(
        "mma.sync.aligned.m16n8k16.row.col.f32.f16.f16.f32 "
        "{%0,%1,%2,%3}, {%4,%5,%6,%7}, {%8,%9}, {%0,%1,%2,%3};"
        : "+f"(c[0]), "+f"(c[1]), "+f"(c[2]), "+f"(c[3])
        : "r"(a[0]), "r"(a[1]), "r"(a[2]), "r"(a[3]), "r"(b[0]), "r"(b[1]));
}

__device__ __forceinline__ void cp_async16(uint32_t dst, const void* src) {
    asm volatile("cp.async.cg.shared.global [%0], [%1], 16;"
                 :: "r"(dst), "l"(__cvta_generic_to_global(src)) : "memory");
}
#define CP_COMMIT() asm volatile("cp.async.commit_group;" ::: "memory")
#define CP_WAIT(n)  asm volatile("cp.async.wait_group %0;" :: "n"(n) : "memory")

// ---------------- kernel 0: x -> fp16 plane, reset globals ----------------
__global__ void hb_split_kernel(const float* __restrict__ x) {
    int i = blockIdx.x * blockDim.x + threadIdx.x;   // over float2 chunks (262144)
    if (i == 0) { g_abssum = 0.0f; g_done = 0; }
    float2 v = reinterpret_cast<const float2*>(x)[i];
    reinterpret_cast<__half2*>(g_xhalf)[i] = __floats2half2_rn(v.x, v.y);
}

// ---------------- kernel 1: fused sign + GEMM + |W| reduce + scale ----------------
__global__ void __launch_bounds__(NTHREADS, 1)
hb_gemm_kernel(const float* __restrict__ W, float* __restrict__ out) {
    extern __shared__ __align__(1024) char smem[];
    const uint32_t sb = smem_u32(smem);

    const int tid  = threadIdx.x;
    const int lane = tid & 31;
    const int wid  = tid >> 5;          // 0..15
    const int wn   = wid & 1;           // 2 warps along N (n32)
    const int wm   = (wid >> 1) & 1;    // 2 warps along M (m32)
    const int kh   = wid >> 2;          // 4 k16-quarters
    const int n0   = blockIdx.x * NT;
    const int nw   = wn * 32;
    const int mwr  = wm * 32;

#define W_OFF(s) (sb + SMEM_W + (uint32_t)(s) * W_STAGE)
#define A_OFF(s) (sb + SMEM_A + (uint32_t)(s) * 8192u)
#define B_OFF(s) (sb + SMEM_B + (uint32_t)(s) * 8192u)

    float c[2][4][4];                   // [m-tile][n-tile][frag], warp tile m32 x n32
#pragma unroll
    for (int mt = 0; mt < 2; mt++)
#pragma unroll
        for (int nt = 0; nt < 4; nt++)
#pragma unroll
            for (int r = 0; r < 4; r++) c[mt][nt][r] = 0.0f;

    float absacc = 0.0f;

    // ldmatrix per-lane coordinates (hoisted loop-invariant swizzled offsets)
    const int ar    = lane & 15;
    const int ac8   = lane >> 4;
    const int brow0 = nw +      (lane & 7) + ((lane >> 4) << 3);
    const int brow1 = nw + 16 + (lane & 7) + ((lane >> 4) << 3);
    const int bc8   = (lane >> 3) & 1;
    const uint32_t ofB0 = SW128((uint32_t)(brow0 * 128 + kh * 32 + bc8 * 16));
    const uint32_t ofB1 = SW128((uint32_t)(brow1 * 128 + kh * 32 + bc8 * 16));
    const uint32_t ofA0 = SW128((uint32_t)((mwr +      ar) * 128 + kh * 32 + ac8 * 16));
    const uint32_t ofA1 = SW128((uint32_t)((mwr + 16 + ar) * 128 + kh * 32 + ac8 * 16));

    // W cp.async coords: 2 x 16B per thread (64 rows x 16 chunks = 1024)
    int wr2[2], wc2[2];
#pragma unroll
    for (int g = 0; g < 2; g++) { int cid = tid + g * NTHREADS; wr2[g] = cid >> 4; wc2[g] = cid & 15; }
    // A cp.async coords: 1 x 16B per thread (64 rows x 8 chunks = 512)
    const int xr = tid >> 3, xc = tid & 7;
    const uint32_t ofAcp = SW128((uint32_t)(xr * 128 + xc * 16));
    // convert-pass coords: thread handles 8 floats (eighth-row)
    const int crow = tid >> 3;
    const int cqc  = tid & 7;
    const uint32_t ofWc  = (uint32_t)(crow * W_PITCH + cqc * 32);
    const uint32_t ofBst = SW128((uint32_t)(crow * 128 + cqc * 16));

#define CPW(it, st) do { \
    int _k0 = (it) * KT; \
    _Pragma("unroll") \
    for (int g = 0; g < 2; g++) \
        cp_async16(W_OFF(st) + (uint32_t)(wr2[g] * W_PITCH + wc2[g] * 16), \
                   W + (size_t)(n0 + wr2[g]) * INCH + _k0 + wc2[g] * 4); \
} while (0)

#define CPA(it, st) do { \
    int _k0 = (it) * KT; \
    cp_async16(A_OFF(st) + ofAcp, g_xhalf + (size_t)xr * INCH + _k0 + xc * 8); \
} while (0)

#define CONVERT(st, bp) do { \
    const uint32_t _W = W_OFF(st) + ofWc; \
    float f[8]; \
    _Pragma("unroll") \
    for (int j = 0; j < 2; j++) \
        asm volatile("ld.shared.v4.f32 {%0,%1,%2,%3}, [%4];" \
                     : "=f"(f[4*j]), "=f"(f[4*j+1]), "=f"(f[4*j+2]), "=f"(f[4*j+3]) \
                     : "r"(_W + j * 16)); \
    _Pragma("unroll") \
    for (int j = 0; j < 8; j++) absacc += fabsf(f[j]); \
    uint32_t p[4]; \
    _Pragma("unroll") \
    for (int j = 0; j < 4; j++) p[j] = sgn_f16(f[2*j]) | (sgn_f16(f[2*j+1]) << 16); \
    asm volatile("st.shared.v4.b32 [%0], {%1,%2,%3,%4};" \
                 :: "r"(B_OFF(bp) + ofBst), \
                    "r"(p[0]), "r"(p[1]), "r"(p[2]), "r"(p[3]) : "memory"); \
} while (0)

#define COMPUTE(st, bp) do { \
    const uint32_t _A = A_OFF(st), _B = B_OFF(bp); \
    uint32_t af[8], bf[8]; \
    ldsm_x4(bf,     _B + ofB0); \
    ldsm_x4(bf + 4, _B + ofB1); \
    ldsm_x4(af,     _A + ofA0); \
    ldsm_x4(af + 4, _A + ofA1); \
    _Pragma("unroll") \
    for (int mt = 0; mt < 2; mt++) { \
        mma_f16(c[mt][0], af + 4 * mt, bf); \
        mma_f16(c[mt][1], af + 4 * mt, bf + 2); \
        mma_f16(c[mt][2], af + 4 * mt, bf + 4); \
        mma_f16(c[mt][3], af + 4 * mt, bf + 6); \
    } \
} while (0)

    // ---- prologue: stages 0..2 in flight ----
    CPW(0, 0); CPA(0, 0); CP_COMMIT();
    CPW(1, 1); CPA(1, 1); CP_COMMIT();
    CPW(2, 2); CPA(2, 2); CP_COMMIT();
    CP_WAIT(2);                 // stage 0 resident
    __syncthreads();
    CONVERT(0, 0);              // W0 -> Bsign(0)

    // ---- main loop: one sync per iter, 5-stage mod-5 ring (race-free recycle) ----
    int ws = 3, rcur = 0;
    uint32_t bpar = 0;
    for (int it = 0; it < NITER; ++it) {
        int rs1 = (rcur + 1 == 5) ? 0 : rcur + 1;
        if (it + 3 < NITER) {
            CPW(it + 3, ws); CPA(it + 3, ws); CP_COMMIT();
            ws = (ws + 1 == 5) ? 0 : ws + 1;
        }
        if (it + 3 < NITER)      CP_WAIT(2);
        else if (it + 2 < NITER) CP_WAIT(1);
        else                     CP_WAIT(0);
        __syncthreads();
        if (it + 1 < NITER) CONVERT(rs1, bpar ^ 1u);
        COMPUTE(rcur, bpar);
        rcur = rs1; bpar ^= 1u;
    }

    // ---- |W| reduce: warp -> CTA ----
#pragma unroll
    for (int o = 16; o > 0; o >>= 1) absacc += __shfl_xor_sync(0xFFFFFFFFu, absacc, o);
    __syncthreads();  // rings dead; smem reused below
    float* comb = reinterpret_cast<float*>(smem);           // 3 x 4096 floats (48KB)
    float* wsum = reinterpret_cast<float*>(smem + 64512);   // 16 floats
    if (lane == 0) wsum[wid] = absacc;

    // ---- kh>0 warps publish partial accumulators (own 32x32 quadrant) ----
    if (kh > 0) {
        float* blk = comb + (kh - 1) * 4096;
#pragma unroll
        for (int mt = 0; mt < 2; mt++)
#pragma unroll
            for (int nt = 0; nt < 4; nt++) {
                int r0 = mwr + mt * 16 + (lane >> 2);
                int cl = nw + nt * 8 + (lane & 3) * 2;
                blk[r0 * 64 + cl]           = c[mt][nt][0];
                blk[r0 * 64 + cl + 1]       = c[mt][nt][1];
                blk[(r0 + 8) * 64 + cl]     = c[mt][nt][2];
                blk[(r0 + 8) * 64 + cl + 1] = c[mt][nt][3];
            }
    }
    __syncthreads();

    // ---- global barrier across all CTAs, then pick up final abs-sum ----
    if (tid == 0) {
        float ctasum = 0.0f;
#pragma unroll
        for (int j = 0; j < 16; j++) ctasum += wsum[j];
        atomicAdd(&g_abssum, ctasum);
        __threadfence();
        atomicAdd(&g_done, 1);
        while (*((volatile int*)&g_done) < NCTAS) __nanosleep(64);
    }
    __syncthreads();
    const float s = (*((volatile float*)&g_abssum)) * (1.0f / ((float)INCH * (float)OUTCH));

    // ---- kh==0 warps combine 3 partials, scale, store ----
    if (kh == 0) {
#pragma unroll
        for (int mt = 0; mt < 2; mt++)
#pragma unroll
            for (int nt = 0; nt < 4; nt++) {
                int r0 = mwr + mt * 16 + (lane >> 2);
                int cl = nw + nt * 8 + (lane & 3) * 2;
                float v0 = c[mt][nt][0], v1 = c[mt][nt][1];
                float v2 = c[mt][nt][2], v3 = c[mt][nt][3];
#pragma unroll
                for (int q = 0; q < 3; q++) {
                    const float* blk = comb + q * 4096;
                    v0 += blk[r0 * 64 + cl];
                    v1 += blk[r0 * 64 + cl + 1];
                    v2 += blk[(r0 + 8) * 64 + cl];
                    v3 += blk[(r0 + 8) * 64 + cl + 1];
                }
                *reinterpret_cast<float2*>(out + (size_t)r0 * OUTCH + n0 + cl) =
                    make_float2(v0 * s, v1 * s);
                *reinterpret_cast<float2*>(out + (size_t)(r0 + 8) * OUTCH + n0 + cl) =
                    make_float2(v2 * s, v3 * s);
            }
    }

#undef CPW
#undef CPA
#undef CONVERT
#undef COMPUTE
#undef W_OFF
#undef A_OFF
#undef B_OFF
}

// ---------------- launch ----------------
extern "C" void kernel_launch(void* const* d_in, const int* in_sizes, int n_in,
                              void* d_out, int out_size) {
    const float* x = (const float*)d_in[0];
    const float* w = (const float*)d_in[1];
    if (n_in >= 2 && in_sizes[0] != BATCH * INCH) { const float* t = x; x = w; w = t; }
    float* out = (float*)d_out;

    cudaFuncSetAttribute(hb_gemm_kernel,
                         cudaFuncAttributeMaxDynamicSharedMemorySize, SMEM_BYTES);

    hb_split_kernel<<<(BATCH * INCH / 2) / 256, 256>>>(x);
    hb_gemm_kernel<<<NCTAS, NTHREADS, SMEM_BYTES>>>(w, out);
}